// round 6
// baseline (speedup 1.0000x reference)
#include <cuda_runtime.h>
#include <cuda_fp16.h>
#include <math.h>

#define BATCH 4
#define CH    128
#define HH    384
#define WW    384
#define HW    (HH*WW)

#define TX 32            // interior tile width
#define TY 6             // interior tile height
#define PX 36            // patch width  (TX + 4)
#define PY 10            // patch height (TY + 4)
#define NP (PX*PY)       // 360 patch pixels
#define NOWN (TX*TY)     // 192 owned pixels
#define THREADS 256
#define GX (WW/TX)       // 12
#define GY (HH/TY)       // 64
#define NBLK (GX*GY*BATCH)

// smem layout (bytes). Patch: 256B per pixel (128 half), 16B-chunk XOR swizzle.
#define SM_NORM  (NP*256)                  // 92160
#define SM_CLS   (SM_NORM + NP*4)          // +1440
#define SM_LIST  (SM_CLS + ((NP+3)&~3))    // +360->364
#define SM_CTR   (SM_LIST + NOWN*4)        // +768
#define SM_TOTAL (SM_CTR + 16)

__device__ float g_acc[BATCH];
__device__ int   g_cnt[BATCH];
__device__ int   g_bnd[BATCH];
__device__ int   g_done;

// ---------------------------------------------------------------------------
__global__ void zero_kernel() {
    if (threadIdx.x == 0) g_done = 0;
    if (threadIdx.x < BATCH) {
        g_acc[threadIdx.x] = 0.0f;
        g_cnt[threadIdx.x] = 0;
        g_bnd[threadIdx.x] = 0;
    }
}

// ---------------------------------------------------------------------------
extern __shared__ char sm[];

__global__ void __launch_bounds__(THREADS, 2)
fused_kernel(const float* __restrict__ er, const int* __restrict__ seg,
             const int* __restrict__ gtb, float* __restrict__ out)
{
    float*         snorm  = (float*)(sm + SM_NORM);
    unsigned char* scls   = (unsigned char*)(sm + SM_CLS);
    int*           slist  = (int*)(sm + SM_LIST);
    int*           s_nsel = (int*)(sm + SM_CTR);
    int*           s_bnd  = s_nsel + 1;
    float*         s_acc  = (float*)(s_nsel + 2);

    const int t  = threadIdx.x;
    const int x0 = blockIdx.x * TX;
    const int y0 = blockIdx.y * TY;
    const int b  = blockIdx.z;

    if (t == 0) { *s_nsel = 0; *s_bnd = 0; *s_acc = 0.0f; }

    // ---- patch pixel slots: p0 = t, p1 = t+256 (if < 360), clamped coords
    const int p0 = t;
    const int p1 = t + THREADS;
    int ry0 = p0 / PX, rx0 = p0 - ry0 * PX;
    int g0 = min(max(y0 - 2 + ry0, 0), HH - 1) * WW + min(max(x0 - 2 + rx0, 0), WW - 1);
    int g1 = 0;
    if (p1 < NP) {
        int ry1 = p1 / PX, rx1 = p1 - ry1 * PX;
        g1 = min(max(y0 - 2 + ry1, 0), HH - 1) * WW + min(max(x0 - 2 + rx1, 0), WW - 1);
    }

    // ---- phase A: load patch (fp32, channel-major gmem) -> fp16 smem + norms
    const float* erb = er + (size_t)b * CH * HW;
    float sq0 = 0.0f, sq1 = 0.0f;
#pragma unroll
    for (int k = 0; k < 16; k++) {          // 16 chunks of 8 channels
        float v0[8];
#pragma unroll
        for (int i = 0; i < 8; i++) v0[i] = erb[(size_t)(k * 8 + i) * HW + g0];
#pragma unroll
        for (int i = 0; i < 8; i++) sq0 += v0[i] * v0[i];
        __half2 h0[4];
#pragma unroll
        for (int i = 0; i < 4; i++) h0[i] = __floats2half2_rn(v0[2 * i], v0[2 * i + 1]);
        *(uint4*)(sm + p0 * 256 + ((k ^ (p0 & 15)) << 4)) = *(uint4*)h0;

        if (p1 < NP) {
            float v1[8];
#pragma unroll
            for (int i = 0; i < 8; i++) v1[i] = erb[(size_t)(k * 8 + i) * HW + g1];
#pragma unroll
            for (int i = 0; i < 8; i++) sq1 += v1[i] * v1[i];
            __half2 h1[4];
#pragma unroll
            for (int i = 0; i < 4; i++) h1[i] = __floats2half2_rn(v1[2 * i], v1[2 * i + 1]);
            *(uint4*)(sm + p1 * 256 + ((k ^ (p1 & 15)) << 4)) = *(uint4*)h1;
        }
    }
    snorm[p0] = 1.0f / fmaxf(sqrtf(sq0), 1e-8f);
    scls[p0]  = (unsigned char)seg[(size_t)(b * 2 + 1) * HW + g0];
    if (p1 < NP) {
        snorm[p1] = 1.0f / fmaxf(sqrtf(sq1), 1e-8f);
        scls[p1]  = (unsigned char)seg[(size_t)(b * 2 + 1) * HW + g1];
    }

    // ---- phase B: masks for owned pixels, warp-aggregated compaction
    if (t < NOWN) {                          // warps 0..5 (full warps)
        int oy = t >> 5, ox = t & 31;
        int gy = y0 + oy, gx = x0 + ox;
        int gp = gy * WW + gx;
        int s1r = seg[(size_t)(b * 2 + 1) * HW + gp];
        int gt  = gtb[(size_t)b * HW + gp];
        if (gt == 255) gt = 0;
        int s1 = s1r; if (s1 == 255) s1 = 0;
        bool bnd   = (gt * s1) > 0;
        bool inter = (gy >= 2) && (gy <= HH - 3) && (gx >= 2) && (gx <= WW - 3);
        bool sel   = bnd && inter;

        unsigned selm = __ballot_sync(0xffffffffu, sel);
        unsigned bndm = __ballot_sync(0xffffffffu, bnd);
        int lane = t & 31;
        int base = 0;
        if (lane == 0) {
            if (selm) base = atomicAdd(s_nsel, __popc(selm));
            if (bndm) atomicOr(s_bnd, 1);
        }
        base = __shfl_sync(0xffffffffu, base, 0);
        if (sel) slist[base + __popc(selm & ((1u << lane) - 1u))] = (oy + 2) * PX + (ox + 2);
    }
    __syncthreads();

    // ---- phase C: dot engine from smem (4 pixels/warp, 8 lanes/pixel)
    const int poff[24] = { -74,-73,-72,-71,-70, -38,-37,-36,-35,-34,
                            -2, -1,  1,  2,     34, 35, 36, 37, 38,
                            70, 71, 72, 73, 74 };
    int nsel = *s_nsel;
    int warp = t >> 5, lane = t & 31, grp = lane >> 3, sub = lane & 7;

    for (int base = 0; base < nsel; base += 32) {
        int idx = base + warp * 4 + grp;
        bool active = idx < nsel;
        int pc = active ? slist[idx] : (2 * PX + 2);
        int swz = pc & 15;
        const uint4* cp = (const uint4*)(sm + pc * 256);
        uint4 ua = cp[sub ^ swz];
        uint4 ub = cp[(sub ^ swz) ^ 8];
        __half2 chv[8];
        *(uint4*)&chv[0] = ua;
        *(uint4*)&chv[4] = ub;
        float invc = snorm[pc];
        unsigned char cc = scls[pc];

        float dots[24];
#pragma unroll
        for (int j = 0; j < 24; j++) {
            int q = pc + poff[j];
            int sq_ = q & 15;
            const uint4* np_ = (const uint4*)(sm + q * 256);
            uint4 na = np_[sub ^ sq_];
            uint4 nb = np_[(sub ^ sq_) ^ 8];
            const __half2* ha = (const __half2*)&na;
            const __half2* hb = (const __half2*)&nb;
            __half2 d = __hmul2(chv[0], ha[0]);
            d = __hfma2(chv[1], ha[1], d);
            d = __hfma2(chv[2], ha[2], d);
            d = __hfma2(chv[3], ha[3], d);
            d = __hfma2(chv[4], hb[0], d);
            d = __hfma2(chv[5], hb[1], d);
            d = __hfma2(chv[6], hb[2], d);
            d = __hfma2(chv[7], hb[3], d);
            float2 f2 = __half22float2(d);
            dots[j] = f2.x + f2.y;
        }
#pragma unroll
        for (int m = 1; m <= 4; m <<= 1) {
#pragma unroll
            for (int j = 0; j < 24; j++)
                dots[j] += __shfl_xor_sync(0xffffffffu, dots[j], m);
        }

        float acc = 0.0f;
        if (active) {
#pragma unroll
            for (int tt = 0; tt < 3; tt++) {
                int j = sub + 8 * tt;
                int q = pc + poff[j];
                float cosv = dots[j] * invc * snorm[q];
                float lab  = (scls[q] == cc) ? 1.0f : 0.0f;
                float e = cosv - lab;
                acc += e * e;
            }
        }
#pragma unroll
        for (int m = 1; m <= 4; m <<= 1)
            acc += __shfl_xor_sync(0xffffffffu, acc, m);
        if (sub == 0 && active) atomicAdd(s_acc, acc);
    }
    __syncthreads();

    // ---- block epilogue + fused finalize
    if (t == 0) {
        if (*s_acc != 0.0f) atomicAdd(&g_acc[b], *s_acc);
        if (nsel) atomicAdd(&g_cnt[b], nsel);
        if (*s_bnd) atomicOr(&g_bnd[b], 1);
        __threadfence();
        int done = atomicAdd(&g_done, 1);
        if (done == NBLK - 1) {
            float tot = 0.0f, nv = 0.0f;
            for (int bb = 0; bb < BATCH; bb++) {
                float lb = g_acc[bb] / fmaxf((float)g_cnt[bb], 1.0f) / 24.0f;
                if (g_bnd[bb]) { tot += lb; nv += 1.0f; }
            }
            tot = tot / fmaxf(nv, 1.0f);
            if (isnan(tot)) tot = 0.0f;
            out[0] = tot;
        }
    }
}

// ---------------------------------------------------------------------------
extern "C" void kernel_launch(void* const* d_in, const int* in_sizes, int n_in,
                              void* d_out, int out_size) {
    const float* er  = (const float*)d_in[0];
    const int*   seg = (const int*)d_in[1];
    const int*   gtb = (const int*)d_in[2];
    float*       out = (float*)d_out;

    cudaFuncSetAttribute(fused_kernel, cudaFuncAttributeMaxDynamicSharedMemorySize, SM_TOTAL);

    zero_kernel<<<1, 32>>>();
    fused_kernel<<<dim3(GX, GY, BATCH), THREADS, SM_TOTAL>>>(er, seg, gtb, out);
}

// round 7
// speedup vs baseline: 1.2699x; 1.2699x over previous
#include <cuda_runtime.h>
#include <cuda_fp16.h>
#include <math.h>

#define BATCH 4
#define CH    128
#define HH    384
#define WW    384
#define HW    (HH*WW)          // 147456
#define NPIX  (BATCH*HW)       // 589824

#define MAXSEL ((HH-4)*(WW-4)*BATCH)      // 577600
#define CTX_BLOCKS ((MAXSEL + 63) / 64)   // 8 warps/block, 8 px/warp

// Scratch (allocation-free: __device__ globals)
__device__ __half        g_Th[(size_t)NPIX * CH]; // [B,H,W,C] fp16 features (151 MB)
__device__ float         g_inv[NPIX];             // 1 / max(||f||, 1e-8)  (fp32-exact)
__device__ unsigned char g_cls[NPIX];             // class (seg_label channel 1)
__device__ int           g_list[NPIX];            // compacted selected pixel ids
__device__ int           g_nsel;
__device__ float         g_acc[BATCH];
__device__ int           g_cnt[BATCH];
__device__ int           g_bnd[BATCH];
__device__ int           g_done;

__constant__ int c_off[24] = {
    -770,-769,-768,-767,-766,
    -386,-385,-384,-383,-382,
      -2,  -1,   1,   2,
     382, 383, 384, 385, 386,
     766, 767, 768, 769, 770 };

// ---------------------------------------------------------------------------
// 0. zero the tiny accumulators
__global__ void zero_kernel() {
    if (threadIdx.x == 0) { g_nsel = 0; g_done = 0; }
    if (threadIdx.x < BATCH) {
        g_acc[threadIdx.x] = 0.0f;
        g_cnt[threadIdx.x] = 0;
        g_bnd[threadIdx.x] = 0;
    }
}

// ---------------------------------------------------------------------------
// 1. transpose [B,C,H,W] -> [B,H,W,C] fp16, fused fp32 inv-norm AND prep
//    (mask + compaction + class byte). Block owns 32 pixels x 128 channels.
__global__ void transpose_kernel(const float* __restrict__ er,
                                 const int* __restrict__ seg,
                                 const int* __restrict__ gtb) {
    __shared__ float tile[32][33];    // [channel][pixel]
    __shared__ float red[8][32];
    int tx = threadIdx.x, ty = threadIdx.y;
    int t  = ty * 32 + tx;
    int p0 = blockIdx.x * 32;
    int b  = blockIdx.y;
    int px = t >> 3;                  // output pixel 0..31
    int j  = t & 7;                   // half2-pair index

    __half2* outp = (__half2*)g_Th + ((size_t)(b * HW) + p0) * (CH / 2);

    float sq = 0.0f;
    for (int c0 = 0; c0 < CH; c0 += 32) {
        if (c0) __syncthreads();
#pragma unroll
        for (int i = 0; i < 4; i++) {
            int c = c0 + ty + 8 * i;
            float v = er[((size_t)(b * CH + c)) * HW + p0 + tx];  // coalesced over tx
            tile[ty + 8 * i][tx] = v;
            sq += v * v;
        }
        __syncthreads();
#pragma unroll
        for (int k = 0; k < 2; k++) {
            int jj = j + 8 * k;
            __half2 h = __floats2half2_rn(tile[2 * jj][px], tile[2 * jj + 1][px]);
            outp[(size_t)px * (CH / 2) + c0 / 2 + jj] = h;
        }
    }
    red[ty][tx] = sq;
    __syncthreads();
    if (ty == 0) {   // warp 0: inv-norm + prep for this block's 32 pixels
        float s = 0.0f;
#pragma unroll
        for (int k = 0; k < 8; k++) s += red[k][tx];
        int rem = p0 + tx;
        int p   = b * HW + rem;
        g_inv[p] = 1.0f / fmaxf(sqrtf(s), 1e-8f);

        int y = rem / WW;
        int x = rem - y * WW;
        int s1r = seg[((size_t)(b * 2 + 1)) * HW + rem];
        int gt  = gtb[p];            if (gt == 255) gt = 0;
        int s1  = s1r;               if (s1 == 255) s1 = 0;
        bool bnd = (gt * s1) > 0;
        bool inter = (y >= 2) && (y <= HH - 3) && (x >= 2) && (x <= WW - 3);
        bool sel = bnd && inter;
        g_cls[p] = (unsigned char)s1r;

        unsigned selm = __ballot_sync(0xffffffffu, sel);
        unsigned bndm = __ballot_sync(0xffffffffu, bnd);
        int base = 0;
        if (tx == 0 && selm) {
            base = atomicAdd(&g_nsel, __popc(selm));
            atomicAdd(&g_cnt[b], __popc(selm));
        }
        if (tx == 0 && bndm) atomicOr(&g_bnd[b], 1);
        base = __shfl_sync(0xffffffffu, base, 0);
        if (sel) g_list[base + __popc(selm & ((1u << tx) - 1u))] = p;
    }
}

// ---------------------------------------------------------------------------
// 2. main: 8 pixels/warp, 4 lanes/pixel (32 ch/lane); 3 groups of 8 neighbors
//    to keep live registers low; packed HFMA2; fused finalize
__global__ void __launch_bounds__(256, 5)
ctx_kernel(float* __restrict__ out) {
    __shared__ float sacc[BATCH];
    int tid  = threadIdx.x;
    int nsel = g_nsel;

    if (blockIdx.x * 64 < nsel) {
        if (tid < BATCH) sacc[tid] = 0.0f;
        __syncthreads();

        int warp = blockIdx.x * 8 + (tid >> 5);
        int lane = tid & 31;
        int grp  = lane >> 2;               // pixel within warp (0..7)
        int sub  = lane & 3;                // lane within pixel (0..3)

        int idx = warp * 8 + grp;
        bool active = idx < nsel;
        int p = active ? g_list[idx] : (2 * WW + 2);

        // center: 32 channels per lane = 4 uint4 (16 half2)
        const uint4* base4 = (const uint4*)(g_Th + (size_t)p * CH);
        __half2 chv[16];
#pragma unroll
        for (int k = 0; k < 4; k++)
            *(uint4*)&chv[4 * k] = base4[sub + 4 * k];
        float invc = g_inv[p];
        unsigned char cp = g_cls[p];

        float acc = 0.0f;
#pragma unroll
        for (int g = 0; g < 3; g++) {
            float dots[8];
#pragma unroll
            for (int jj = 0; jj < 8; jj++) {
                int q = p + c_off[g * 8 + jj];
                const uint4* nb4 = (const uint4*)(g_Th + (size_t)q * CH);
                uint4 n0 = nb4[sub], n1 = nb4[sub + 4], n2 = nb4[sub + 8], n3 = nb4[sub + 12];
                const __half2* h0 = (const __half2*)&n0;
                const __half2* h1 = (const __half2*)&n1;
                const __half2* h2 = (const __half2*)&n2;
                const __half2* h3 = (const __half2*)&n3;
                __half2 d = __hmul2(chv[0], h0[0]);
                d = __hfma2(chv[1],  h0[1], d);
                d = __hfma2(chv[2],  h0[2], d);
                d = __hfma2(chv[3],  h0[3], d);
                d = __hfma2(chv[4],  h1[0], d);
                d = __hfma2(chv[5],  h1[1], d);
                d = __hfma2(chv[6],  h1[2], d);
                d = __hfma2(chv[7],  h1[3], d);
                d = __hfma2(chv[8],  h2[0], d);
                d = __hfma2(chv[9],  h2[1], d);
                d = __hfma2(chv[10], h2[2], d);
                d = __hfma2(chv[11], h2[3], d);
                d = __hfma2(chv[12], h3[0], d);
                d = __hfma2(chv[13], h3[1], d);
                d = __hfma2(chv[14], h3[2], d);
                d = __hfma2(chv[15], h3[3], d);
                float2 f2 = __half22float2(d);
                dots[jj] = f2.x + f2.y;
            }
            // 8 independent 2-stage butterflies over the 4-lane group
#pragma unroll
            for (int m = 1; m <= 2; m <<= 1) {
#pragma unroll
                for (int jj = 0; jj < 8; jj++)
                    dots[jj] += __shfl_xor_sync(0xffffffffu, dots[jj], m);
            }
            // epilogue for this group: lane sub handles neighbors sub, sub+4
            if (active) {
#pragma unroll
                for (int tt = 0; tt < 2; tt++) {
                    int jj = sub + 4 * tt;
                    int q = p + c_off[g * 8 + jj];
                    float cosv = dots[jj] * invc * g_inv[q];
                    float lab  = (g_cls[q] == cp) ? 1.0f : 0.0f;
                    float e = cosv - lab;
                    acc += e * e;
                }
            }
        }
#pragma unroll
        for (int m = 1; m <= 2; m <<= 1)
            acc += __shfl_xor_sync(0xffffffffu, acc, m);
        if (sub == 0 && active) atomicAdd(&sacc[p / HW], acc);

        __syncthreads();
        if (tid < BATCH) {
            float v = sacc[tid];
            if (v != 0.0f) atomicAdd(&g_acc[tid], v);
        }
        __syncthreads();
    }

    // fused finalize: last block to retire computes the scalar output
    if (tid == 0) {
        __threadfence();
        int done = atomicAdd(&g_done, 1);
        if (done == (int)gridDim.x - 1) {
            float tot = 0.0f, nv = 0.0f;
            for (int b = 0; b < BATCH; b++) {
                float lb = g_acc[b] / fmaxf((float)g_cnt[b], 1.0f) / 24.0f;
                if (g_bnd[b]) { tot += lb; nv += 1.0f; }
            }
            tot = tot / fmaxf(nv, 1.0f);
            if (isnan(tot)) tot = 0.0f;
            out[0] = tot;
        }
    }
}

// ---------------------------------------------------------------------------
extern "C" void kernel_launch(void* const* d_in, const int* in_sizes, int n_in,
                              void* d_out, int out_size) {
    const float* er  = (const float*)d_in[0];
    const int*   seg = (const int*)d_in[1];
    const int*   gtb = (const int*)d_in[2];
    float*       out = (float*)d_out;

    zero_kernel<<<1, 32>>>();
    transpose_kernel<<<dim3(HW / 32, BATCH), dim3(32, 8)>>>(er, seg, gtb);
    ctx_kernel<<<CTX_BLOCKS, 256>>>(out);
}